// round 15
// baseline (speedup 1.0000x reference)
#include <cuda_runtime.h>
#include <cuda_fp16.h>
#include <cstdint>
#include <math.h>

#define BROWS 4096
#define DIN   2048
#define DHID  3584
#define DOUT  2048

// ---------------- scratch (static __device__, no allocation) ----------------
__device__ __align__(16) __half g_xh  [(size_t)BROWS*DIN];
__device__ __align__(16) __half g_xl  [(size_t)BROWS*DIN];
__device__ __align__(16) __half g_wflh[(size_t)DHID*DIN];
__device__ __align__(16) __half g_wfll[(size_t)DHID*DIN];
__device__ __align__(16) __half g_wmh [(size_t)DOUT*DHID];
__device__ __align__(16) __half g_wml [(size_t)DOUT*DHID];
__device__ __align__(16) __half g_wfh [(size_t)DOUT*DHID];   // flipped female hi
__device__ __align__(16) __half g_wfl2[(size_t)DOUT*DHID];   // flipped female lo
__device__ __align__(16) __half g_xeh [(size_t)BROWS*DHID];
__device__ __align__(16) __half g_xel [(size_t)BROWS*DHID];
__device__ __align__(16) float  g_male[(size_t)BROWS*DOUT];
__device__ __align__(16) float  g_fem [(size_t)BROWS*DOUT];

// ---------------- PTX helpers (generic sm_80-era, legal on compute_103) ----
__device__ __forceinline__ uint32_t smem_u32(const void* p) {
    uint32_t a;
    asm("{ .reg .u64 t; cvta.to.shared.u64 t, %1; cvt.u32.u64 %0, t; }" : "=r"(a) : "l"(p));
    return a;
}
#define CP16(dst, src) asm volatile("cp.async.cg.shared.global [%0], [%1], 16;" :: "r"(dst), "l"(src))
#define CP_COMMIT()    asm volatile("cp.async.commit_group;" ::: "memory")
#define CP_WAIT1()     asm volatile("cp.async.wait_group 1;" ::: "memory")
#define CP_WAIT0()     asm volatile("cp.async.wait_group 0;" ::: "memory")

__device__ __forceinline__ void ldsm4(uint32_t* r, uint32_t addr) {
    asm volatile("ldmatrix.sync.aligned.m8n8.x4.shared.b16 {%0,%1,%2,%3}, [%4];"
                 : "=r"(r[0]), "=r"(r[1]), "=r"(r[2]), "=r"(r[3]) : "r"(addr));
}
__device__ __forceinline__ void mma16816(float* c, const uint32_t* a, const uint32_t* b) {
    asm volatile(
        "mma.sync.aligned.m16n8k16.row.col.f32.f16.f16.f32 "
        "{%0,%1,%2,%3}, {%4,%5,%6,%7}, {%8,%9}, {%0,%1,%2,%3};"
        : "+f"(c[0]), "+f"(c[1]), "+f"(c[2]), "+f"(c[3])
        : "r"(a[0]), "r"(a[1]), "r"(a[2]), "r"(a[3]), "r"(b[0]), "r"(b[1]));
}

// ---------------- GEMM config: BM=BN=128, BK=64, 512 thr, 2-stage ----------------
#define GTHREADS 512
#define GBM 128
#define GBN 128
#define GBK 64
#define LROW 72                          // 64 + 8 halfs pad (144B stride)
#define TILE_B (GBM * LROW * 2)          // 18432 B per tile
#define OFF_AH 0
#define OFF_AL TILE_B
#define OFF_BH (2 * TILE_B)
#define OFF_BL (3 * TILE_B)
#define STAGE  (4 * TILE_B)              // 73728 B
#define GSMEM  (2 * STAGE)               // 147456 B
#define INV2048 4.8828125e-4f

__device__ __forceinline__ void cp_stage(
    uint32_t base, const __half* __restrict__ Ah, const __half* __restrict__ Al,
    const __half* __restrict__ Bh, const __half* __restrict__ Bl,
    int rowBlock, int colBlock, int K, int kt, int t)
{
    // each tile: 128 rows x 8 chunks(16B) = 1024 chunks; 2 per thread per tile
    #pragma unroll
    for (int i = 0; i < 2; i++) {
        int c = t + i * GTHREADS;
        int r = c >> 3, kc = (c & 7) * 8;               // kc in halves
        uint32_t doff = (uint32_t)((r * LROW + kc) * 2);
        size_t ga = (size_t)(rowBlock + r) * K + kt + kc;
        size_t gb = (size_t)(colBlock + r) * K + kt + kc;
        CP16(base + OFF_AH + doff, Ah + ga);
        CP16(base + OFF_AL + doff, Al + ga);
        CP16(base + OFF_BH + doff, Bh + gb);
        CP16(base + OFF_BL + doff, Bl + gb);
    }
}

// C = (Ah + Al/2048) @ (Bh + Bl/2048)^T, al*bl dropped.
// EPI=1: phase-shift epilogue, split-write half C0(hi)/C1(lo*2048).
// EPI=0: z selects weights/outputs; float write.
template<int EPI>
__global__ void __launch_bounds__(GTHREADS, 1)
gemm_fp16x3(const __half* __restrict__ Ah, const __half* __restrict__ Al,
            const __half* __restrict__ Bh0, const __half* __restrict__ Bl0,
            const __half* __restrict__ Bh1, const __half* __restrict__ Bl1,
            void* __restrict__ C0v, void* __restrict__ C1v,
            int K, int N)
{
    extern __shared__ char smem_raw[];
    const uint32_t sb = smem_u32(smem_raw);
    const int t = threadIdx.x, lane = t & 31, wid = t >> 5;
    const int wn = wid & 3, wm = wid >> 2;     // 4(M) x 4(N) warps; warp tile 32x32
    const int rowBlock = blockIdx.y * GBM;
    const int colBlock = blockIdx.x * GBN;

    const __half* Bh = (EPI == 1 || blockIdx.z == 0) ? Bh0 : Bh1;
    const __half* Bl = (EPI == 1 || blockIdx.z == 0) ? Bl0 : Bl1;

    float acc_hh[2][4][4];
    float acc_x [2][4][4];
    #pragma unroll
    for (int mi = 0; mi < 2; mi++)
        #pragma unroll
        for (int ni = 0; ni < 4; ni++)
            #pragma unroll
            for (int e = 0; e < 4; e++) { acc_hh[mi][ni][e] = 0.f; acc_x[mi][ni][e] = 0.f; }

    const int NK = K / GBK;
    cp_stage(sb, Ah, Al, Bh, Bl, rowBlock, colBlock, K, 0, t);
    CP_COMMIT();

    // A ldsm4 lane mapping (m16 x k16 tile)
    const int a_row = (lane & 15), a_col = ((lane >> 4) << 3);
    // B ldsm4 pairing: 4 groups of 8 lanes -> tiles (n, kk),(n, kk+8),(n+1, kk),(n+1, kk+8)
    const int b_row = (lane & 7);
    const int b_nsub = ((lane >> 4) & 1);          // 0/1 within the ni pair
    const int b_col  = (((lane >> 3) & 1) << 3);   // 0/8 k-offset

    for (int it = 0; it < NK; it++) {
        if (it + 1 < NK) {
            cp_stage(sb + ((it + 1) & 1) * STAGE, Ah, Al, Bh, Bl,
                     rowBlock, colBlock, K, (it + 1) * GBK, t);
            CP_COMMIT();
            CP_WAIT1();
        } else {
            CP_WAIT0();
        }
        __syncthreads();

        const uint32_t base = sb + (it & 1) * STAGE;
        #pragma unroll
        for (int kk = 0; kk < GBK; kk += 16) {
            // B: 2 ldsm4 per limb -> fragments for 4 n-tiles
            uint32_t b_h[4][2], b_l[4][2];
            #pragma unroll
            for (int p = 0; p < 2; p++) {
                int row = wn * 32 + (p * 2 + b_nsub) * 8 + b_row;
                uint32_t off = (uint32_t)((row * LROW + kk + b_col) * 2);
                uint32_t r4[4];
                ldsm4(r4, base + OFF_BH + off);
                b_h[p*2][0] = r4[0]; b_h[p*2][1] = r4[1];
                b_h[p*2+1][0] = r4[2]; b_h[p*2+1][1] = r4[3];
                ldsm4(r4, base + OFF_BL + off);
                b_l[p*2][0] = r4[0]; b_l[p*2][1] = r4[1];
                b_l[p*2+1][0] = r4[2]; b_l[p*2+1][1] = r4[3];
            }
            uint32_t a_h[2][4], a_l[2][4];
            #pragma unroll
            for (int mi = 0; mi < 2; mi++) {
                int row = wm * 32 + mi * 16 + a_row;
                uint32_t off = (uint32_t)((row * LROW + kk + a_col) * 2);
                ldsm4(a_h[mi], base + OFF_AH + off);
                ldsm4(a_l[mi], base + OFF_AL + off);
            }
            // term-grouped issue: 8 independent mma between writes to same acc
            #pragma unroll
            for (int mi = 0; mi < 2; mi++)
                #pragma unroll
                for (int ni = 0; ni < 4; ni++)
                    mma16816(acc_hh[mi][ni], a_h[mi], b_h[ni]);
            #pragma unroll
            for (int mi = 0; mi < 2; mi++)
                #pragma unroll
                for (int ni = 0; ni < 4; ni++)
                    mma16816(acc_x[mi][ni], a_h[mi], b_l[ni]);
            #pragma unroll
            for (int mi = 0; mi < 2; mi++)
                #pragma unroll
                for (int ni = 0; ni < 4; ni++)
                    mma16816(acc_x[mi][ni], a_l[mi], b_h[ni]);
        }
        __syncthreads();
    }

    // ---------------- epilogue ----------------
    #pragma unroll
    for (int mi = 0; mi < 2; mi++) {
        #pragma unroll
        for (int ni = 0; ni < 4; ni++) {
            float v0 = acc_hh[mi][ni][0] + acc_x[mi][ni][0] * INV2048;
            float v1 = acc_hh[mi][ni][1] + acc_x[mi][ni][1] * INV2048;
            float v2 = acc_hh[mi][ni][2] + acc_x[mi][ni][2] * INV2048;
            float v3 = acc_hh[mi][ni][3] + acc_x[mi][ni][3] * INV2048;
            int r0 = rowBlock + wm * 32 + mi * 16 + (lane >> 2);
            int r1 = r0 + 8;
            int c  = colBlock + wn * 32 + ni * 8 + (lane & 3) * 2;
            if (EPI == 1) {
                int o = c & 511;
                if (o == 0) {
                    int ci = c >> 9;
                    float ph = 6.28318530717958647692f * (float)ci / 7.0f;
                    float p0 = cosf(ph), p1 = sinf(ph);
                    v0 *= p0; v1 *= p1; v2 *= p0; v3 *= p1;
                }
                __half* Ch = (__half*)C0v;
                __half* Cl = (__half*)C1v;
                __half h0 = __float2half_rn(v0), h1 = __float2half_rn(v1);
                __half h2 = __float2half_rn(v2), h3 = __float2half_rn(v3);
                __half l0 = __float2half_rn((v0 - __half2float(h0)) * 2048.f);
                __half l1 = __float2half_rn((v1 - __half2float(h1)) * 2048.f);
                __half l2 = __float2half_rn((v2 - __half2float(h2)) * 2048.f);
                __half l3 = __float2half_rn((v3 - __half2float(h3)) * 2048.f);
                *(__half2*)(Ch + (size_t)r0 * N + c) = __halves2half2(h0, h1);
                *(__half2*)(Ch + (size_t)r1 * N + c) = __halves2half2(h2, h3);
                *(__half2*)(Cl + (size_t)r0 * N + c) = __halves2half2(l0, l1);
                *(__half2*)(Cl + (size_t)r1 * N + c) = __halves2half2(l2, l3);
            } else {
                float* Cf = (blockIdx.z == 0) ? (float*)C0v : (float*)C1v;
                *(float2*)(Cf + (size_t)r0 * N + c) = make_float2(v0, v1);
                *(float2*)(Cf + (size_t)r1 * N + c) = make_float2(v2, v3);
            }
        }
    }
}

// ---------------- elementwise kernels ----------------
__device__ __forceinline__ float blockReduceSum(float v) {
    __shared__ float sh[33];
    int lane = threadIdx.x & 31, wid = threadIdx.x >> 5;
    #pragma unroll
    for (int o = 16; o; o >>= 1) v += __shfl_down_sync(0xffffffffu, v, o);
    if (lane == 0) sh[wid] = v;
    __syncthreads();
    if (wid == 0) {
        v = (threadIdx.x < (blockDim.x >> 5)) ? sh[lane] : 0.f;
        #pragma unroll
        for (int o = 16; o; o >>= 1) v += __shfl_down_sync(0xffffffffu, v, o);
        if (lane == 0) sh[32] = v;
    }
    __syncthreads();
    return sh[32];
}

__device__ __forceinline__ void split_store(__half* hi, __half* lo, size_t idx2, float a, float b) {
    __half ha = __float2half_rn(a), hb = __float2half_rn(b);
    __half la = __float2half_rn((a - __half2float(ha)) * 2048.f);
    __half lb = __float2half_rn((b - __half2float(hb)) * 2048.f);
    ((__half2*)hi)[idx2] = __halves2half2(ha, hb);
    ((__half2*)lo)[idx2] = __halves2half2(la, lb);
}

// fused: vesica row scale + scaled split of x
__global__ void __launch_bounds__(256) k_scale_split(const float* __restrict__ x) {
    int b  = blockIdx.x;
    int bp = (b == 0) ? (BROWS - 1) : (b - 1);
    const float4* r0 = (const float4*)(x + (size_t)b  * DIN);
    const float4* r1 = (const float4*)(x + (size_t)bp * DIN);
    float ss = 0.f;
    float4 va[2];
    #pragma unroll
    for (int j = 0; j < 2; j++) {
        int i = threadIdx.x + j * 256;
        float4 a = r0[i], c = r1[i];
        va[j] = a;
        float dx = a.x - c.x, dy = a.y - c.y, dz = a.z - c.z, dw = a.w - c.w;
        ss += dx*dx + dy*dy + dz*dz + dw*dw;
    }
    ss = blockReduceSum(ss);          // broadcast
    float dist = sqrtf(ss);
    float s = 1.f + fmaxf(0.f, 1.f - fabsf(dist - 1.f));
    size_t rowBase = (size_t)b * (DIN / 4);
    #pragma unroll
    for (int j = 0; j < 2; j++) {
        size_t i4 = rowBase + threadIdx.x + j * 256;
        split_store(g_xh, g_xl, i4 * 2 + 0, va[j].x * s, va[j].y * s);
        split_store(g_xh, g_xl, i4 * 2 + 1, va[j].z * s, va[j].w * s);
    }
}

__global__ void __launch_bounds__(256) k_split(const float* __restrict__ src,
                                               __half* __restrict__ hi, __half* __restrict__ lo,
                                               size_t n4) {
    size_t i = (size_t)blockIdx.x * 256 + threadIdx.x;
    if (i >= n4) return;
    float4 v = ((const float4*)src)[i];
    split_store(hi, lo, i * 2 + 0, v.x, v.y);
    split_store(hi, lo, i * 2 + 1, v.z, v.w);
}

__global__ void __launch_bounds__(256) k_split_flip(const float* __restrict__ src,
                                                    __half* __restrict__ hi, __half* __restrict__ lo) {
    size_t i = (size_t)blockIdx.x * 256 + threadIdx.x;   // float4 index over [DOUT, DHID]
    if (i >= (size_t)DOUT * DHID / 4) return;
    int o  = (int)(i / (DHID / 4));
    int h4 = (int)(i % (DHID / 4)) * 4;
    float4 v = *(const float4*)(src + (size_t)o * DHID + (DHID - 4 - h4));
    split_store(hi, lo, i * 2 + 0, v.w, v.z);
    split_store(hi, lo, i * 2 + 1, v.y, v.x);
}

__global__ void __launch_bounds__(256) k_final(float* __restrict__ out) {
    int b = blockIdx.x;
    const float4* mr = (const float4*)(g_male + (size_t)b * DOUT);
    const float4* fr = (const float4*)(g_fem  + (size_t)b * DOUT);
    int i0 = threadIdx.x, i1 = threadIdx.x + 256;
    float4 m0 = mr[i0], m1 = mr[i1];
    float4 f0 = fr[i0], f1 = fr[i1];
    float s = m0.x*f0.x + m0.y*f0.y + m0.z*f0.z + m0.w*f0.w
            + m1.x*f1.x + m1.y*f1.y + m1.z*f1.z + m1.w*f1.w;
    s = blockReduceSum(s);
    float pl = 1.f / (1.f + expf(-s));
    float om = 1.f - pl;
    float4* o4 = (float4*)(out + (size_t)b * DOUT);
    o4[i0] = make_float4(pl*m0.x + om*f0.x, pl*m0.y + om*f0.y,
                         pl*m0.z + om*f0.z, pl*m0.w + om*f0.w);
    o4[i1] = make_float4(pl*m1.x + om*f1.x, pl*m1.y + om*f1.y,
                         pl*m1.z + om*f1.z, pl*m1.w + om*f1.w);
}

// ---------------- launch ----------------
extern "C" void kernel_launch(void* const* d_in, const int* in_sizes, int n_in,
                              void* d_out, int out_size) {
    const float* x   = (const float*)d_in[0];   // [4096, 2048]
    const float* wfl = (const float*)d_in[1];   // [3584, 2048]
    const float* wm  = (const float*)d_in[2];   // [2048, 3584]
    const float* wfe = (const float*)d_in[3];   // [2048, 3584]
    float* out = (float*)d_out;

    __half *xh, *xl, *wflh, *wfll, *wmh, *wml, *wfh, *wfl2, *xeh, *xel;
    float *male, *fem;
    cudaGetSymbolAddress((void**)&xh,   g_xh);
    cudaGetSymbolAddress((void**)&xl,   g_xl);
    cudaGetSymbolAddress((void**)&wflh, g_wflh);
    cudaGetSymbolAddress((void**)&wfll, g_wfll);
    cudaGetSymbolAddress((void**)&wmh,  g_wmh);
    cudaGetSymbolAddress((void**)&wml,  g_wml);
    cudaGetSymbolAddress((void**)&wfh,  g_wfh);
    cudaGetSymbolAddress((void**)&wfl2, g_wfl2);
    cudaGetSymbolAddress((void**)&xeh,  g_xeh);
    cudaGetSymbolAddress((void**)&xel,  g_xel);
    cudaGetSymbolAddress((void**)&male, g_male);
    cudaGetSymbolAddress((void**)&fem,  g_fem);

    cudaFuncSetAttribute(gemm_fp16x3<1>, cudaFuncAttributeMaxDynamicSharedMemorySize, GSMEM);
    cudaFuncSetAttribute(gemm_fp16x3<0>, cudaFuncAttributeMaxDynamicSharedMemorySize, GSMEM);

    // 1) vesica scale + x split (fused) and weight splits
    k_scale_split<<<BROWS, 256>>>(x);
    k_split<<<(unsigned)(((size_t)DHID * DIN / 4 + 255) / 256), 256>>>(wfl, wflh, wfll, (size_t)DHID * DIN / 4);
    k_split<<<(unsigned)(((size_t)DOUT * DHID / 4 + 255) / 256), 256>>>(wm, wmh, wml, (size_t)DOUT * DHID / 4);
    k_split_flip<<<(unsigned)(((size_t)DOUT * DHID / 4 + 255) / 256), 256>>>(wfe, wfh, wfl2);

    // 2) GEMM1 (3-term): x_expanded with phase epilogue + split write
    {
        dim3 grid(DHID / GBN, BROWS / GBM, 1);
        gemm_fp16x3<1><<<grid, GTHREADS, GSMEM>>>(xh, xl, wflh, wfll, wflh, wfll,
                                                  xeh, xel, DIN, DHID);
    }

    // 3) GEMM2 (3-term; z=0 male / z=1 female): xexp @ W^T
    {
        dim3 grid(DOUT / GBN, BROWS / GBM, 2);
        gemm_fp16x3<0><<<grid, GTHREADS, GSMEM>>>(xeh, xel, wmh, wml, wfh, wfl2,
                                                  male, fem, DHID, DOUT);
    }

    // 4) phase-lock blend
    k_final<<<BROWS, 256>>>(out);
}

// round 17
// speedup vs baseline: 1.0237x; 1.0237x over previous
#include <cuda_runtime.h>
#include <cuda_fp16.h>
#include <cstdint>
#include <math.h>

#define BROWS 4096
#define DIN   2048
#define DHID  3584
#define DOUT  2048

// ---------------- scratch (static __device__, no allocation) ----------------
// lo limbs stored at TRUE scale (may be fp16 subnormal; exact enough for the
// correction term). All three limb products share ONE fp32 accumulator.
__device__ __align__(16) __half g_xh  [(size_t)BROWS*DIN];
__device__ __align__(16) __half g_xl  [(size_t)BROWS*DIN];
__device__ __align__(16) __half g_wflh[(size_t)DHID*DIN];
__device__ __align__(16) __half g_wfll[(size_t)DHID*DIN];
__device__ __align__(16) __half g_wmh [(size_t)DOUT*DHID];
__device__ __align__(16) __half g_wml [(size_t)DOUT*DHID];
__device__ __align__(16) __half g_wfh [(size_t)DOUT*DHID];   // flipped female hi
__device__ __align__(16) __half g_wfl2[(size_t)DOUT*DHID];   // flipped female lo
__device__ __align__(16) __half g_xeh [(size_t)BROWS*DHID];
__device__ __align__(16) __half g_xel [(size_t)BROWS*DHID];
__device__ __align__(16) float  g_male[(size_t)BROWS*DOUT];
__device__ __align__(16) float  g_fem [(size_t)BROWS*DOUT];

// ---------------- PTX helpers (generic sm_80-era, legal on compute_103) ----
__device__ __forceinline__ uint32_t smem_u32(const void* p) {
    uint32_t a;
    asm("{ .reg .u64 t; cvta.to.shared.u64 t, %1; cvt.u32.u64 %0, t; }" : "=r"(a) : "l"(p));
    return a;
}
#define CP16(dst, src) asm volatile("cp.async.cg.shared.global [%0], [%1], 16;" :: "r"(dst), "l"(src))
#define CP_COMMIT()    asm volatile("cp.async.commit_group;" ::: "memory")
#define CP_WAIT1()     asm volatile("cp.async.wait_group 1;" ::: "memory")
#define CP_WAIT0()     asm volatile("cp.async.wait_group 0;" ::: "memory")

__device__ __forceinline__ void ldsm4(uint32_t* r, uint32_t addr) {
    asm volatile("ldmatrix.sync.aligned.m8n8.x4.shared.b16 {%0,%1,%2,%3}, [%4];"
                 : "=r"(r[0]), "=r"(r[1]), "=r"(r[2]), "=r"(r[3]) : "r"(addr));
}
__device__ __forceinline__ void mma16816(float* c, const uint32_t* a, const uint32_t* b) {
    asm volatile(
        "mma.sync.aligned.m16n8k16.row.col.f32.f16.f16.f32 "
        "{%0,%1,%2,%3}, {%4,%5,%6,%7}, {%8,%9}, {%0,%1,%2,%3};"
        : "+f"(c[0]), "+f"(c[1]), "+f"(c[2]), "+f"(c[3])
        : "r"(a[0]), "r"(a[1]), "r"(a[2]), "r"(a[3]), "r"(b[0]), "r"(b[1]));
}

// ---------------- GEMM config: BM=256, BN=128, BK=64, 256 thr, 2-stage ------
#define GTHREADS 256
#define GBM 256
#define GBN 128
#define GBK 64
#define LROW 72                          // 64 + 8 halfs pad (144B stride)
#define A_TILE_B (GBM * LROW * 2)        // 36864 B per limb
#define B_TILE_B (GBN * LROW * 2)        // 18432 B per limb
#define OFF_AH 0
#define OFF_AL A_TILE_B
#define OFF_BH (2 * A_TILE_B)
#define OFF_BL (2 * A_TILE_B + B_TILE_B)
#define STAGE  (2 * A_TILE_B + 2 * B_TILE_B)   // 110592 B
#define GSMEM  (2 * STAGE)                     // 221184 B

__device__ __forceinline__ void cp_stage(
    uint32_t base, const __half* __restrict__ Ah, const __half* __restrict__ Al,
    const __half* __restrict__ Bh, const __half* __restrict__ Bl,
    int rowBlock, int colBlock, int K, int kt, int t)
{
    // A: 256 rows x 8 chunks(16B) = 2048 chunks per limb
    #pragma unroll
    for (int i = 0; i < 8; i++) {
        int c = t + i * GTHREADS;
        int r = c >> 3, kc = (c & 7) * 8;
        uint32_t doff = (uint32_t)((r * LROW + kc) * 2);
        size_t ga = (size_t)(rowBlock + r) * K + kt + kc;
        CP16(base + OFF_AH + doff, Ah + ga);
        CP16(base + OFF_AL + doff, Al + ga);
    }
    // B: 128 rows x 8 chunks = 1024 chunks per limb
    #pragma unroll
    for (int i = 0; i < 4; i++) {
        int c = t + i * GTHREADS;
        int r = c >> 3, kc = (c & 7) * 8;
        uint32_t doff = (uint32_t)((r * LROW + kc) * 2);
        size_t gb = (size_t)(colBlock + r) * K + kt + kc;
        CP16(base + OFF_BH + doff, Bh + gb);
        CP16(base + OFF_BL + doff, Bl + gb);
    }
}

// C = (Ah + Al) @ (Bh + Bl)^T, al*bl dropped; all terms in ONE fp32 acc.
// EPI=1: phase-shift epilogue, true-scale split write to half C0(hi)/C1(lo).
// EPI=0: z selects weights/outputs; float write.
template<int EPI>
__global__ void __launch_bounds__(GTHREADS, 1)
gemm_fp16x3(const __half* __restrict__ Ah, const __half* __restrict__ Al,
            const __half* __restrict__ Bh0, const __half* __restrict__ Bl0,
            const __half* __restrict__ Bh1, const __half* __restrict__ Bl1,
            void* __restrict__ C0v, void* __restrict__ C1v,
            int K, int N)
{
    extern __shared__ char smem_raw[];
    const uint32_t sb = smem_u32(smem_raw);
    const int t = threadIdx.x, lane = t & 31, wid = t >> 5;
    const int wm = wid >> 1, wn = wid & 1;     // 4(M) x 2(N) warps; warp tile 64x64
    const int rowBlock = blockIdx.y * GBM;
    const int colBlock = blockIdx.x * GBN;

    const __half* Bh = (EPI == 1 || blockIdx.z == 0) ? Bh0 : Bh1;
    const __half* Bl = (EPI == 1 || blockIdx.z == 0) ? Bl0 : Bl1;

    float acc[4][8][4];                        // 128 regs: 4 mi x 8 ni x 4
    #pragma unroll
    for (int mi = 0; mi < 4; mi++)
        #pragma unroll
        for (int ni = 0; ni < 8; ni++)
            #pragma unroll
            for (int e = 0; e < 4; e++) acc[mi][ni][e] = 0.f;

    const int NK = K / GBK;
    cp_stage(sb, Ah, Al, Bh, Bl, rowBlock, colBlock, K, 0, t);
    CP_COMMIT();

    const int a_row = (lane & 15), a_col = ((lane >> 4) << 3);
    const int b_row = (lane & 7);
    const int b_nsub = ((lane >> 4) & 1);
    const int b_col  = (((lane >> 3) & 1) << 3);

    for (int it = 0; it < NK; it++) {
        if (it + 1 < NK) {
            cp_stage(sb + ((it + 1) & 1) * STAGE, Ah, Al, Bh, Bl,
                     rowBlock, colBlock, K, (it + 1) * GBK, t);
            CP_COMMIT();
            CP_WAIT1();
        } else {
            CP_WAIT0();
        }
        __syncthreads();

        const uint32_t base = sb + (it & 1) * STAGE;
        #pragma unroll
        for (int kk = 0; kk < GBK; kk += 16) {
            uint32_t a_h[4][4], a_l[4][4];
            #pragma unroll
            for (int mi = 0; mi < 4; mi++) {
                int row = wm * 64 + mi * 16 + a_row;
                uint32_t off = (uint32_t)((row * LROW + kk + a_col) * 2);
                ldsm4(a_h[mi], base + OFF_AH + off);
                ldsm4(a_l[mi], base + OFF_AL + off);
            }
            // B in 4 pairs of n-tiles; small live set, 8 independent mma per term
            #pragma unroll
            for (int p = 0; p < 4; p++) {
                int row = wn * 64 + (p * 2 + b_nsub) * 8 + b_row;
                uint32_t off = (uint32_t)((row * LROW + kk + b_col) * 2);
                uint32_t bh4[4], bl4[4];
                ldsm4(bh4, base + OFF_BH + off);
                ldsm4(bl4, base + OFF_BL + off);
                // term hh
                #pragma unroll
                for (int mi = 0; mi < 4; mi++) {
                    mma16816(acc[mi][p*2+0], a_h[mi], bh4 + 0);
                    mma16816(acc[mi][p*2+1], a_h[mi], bh4 + 2);
                }
                // term h*l
                #pragma unroll
                for (int mi = 0; mi < 4; mi++) {
                    mma16816(acc[mi][p*2+0], a_h[mi], bl4 + 0);
                    mma16816(acc[mi][p*2+1], a_h[mi], bl4 + 2);
                }
                // term l*h
                #pragma unroll
                for (int mi = 0; mi < 4; mi++) {
                    mma16816(acc[mi][p*2+0], a_l[mi], bh4 + 0);
                    mma16816(acc[mi][p*2+1], a_l[mi], bh4 + 2);
                }
            }
        }
        __syncthreads();
    }

    // ---------------- epilogue ----------------
    #pragma unroll
    for (int mi = 0; mi < 4; mi++) {
        #pragma unroll
        for (int ni = 0; ni < 8; ni++) {
            float v0 = acc[mi][ni][0];
            float v1 = acc[mi][ni][1];
            float v2 = acc[mi][ni][2];
            float v3 = acc[mi][ni][3];
            int r0 = rowBlock + wm * 64 + mi * 16 + (lane >> 2);
            int r1 = r0 + 8;
            int c  = colBlock + wn * 64 + ni * 8 + (lane & 3) * 2;
            if (EPI == 1) {
                int o = c & 511;
                if (o == 0) {
                    int ci = c >> 9;
                    float ph = 6.28318530717958647692f * (float)ci / 7.0f;
                    float p0 = cosf(ph), p1 = sinf(ph);
                    v0 *= p0; v1 *= p1; v2 *= p0; v3 *= p1;
                }
                __half* Ch = (__half*)C0v;
                __half* Cl = (__half*)C1v;
                __half h0 = __float2half_rn(v0), h1 = __float2half_rn(v1);
                __half h2 = __float2half_rn(v2), h3 = __float2half_rn(v3);
                __half l0 = __float2half_rn(v0 - __half2float(h0));
                __half l1 = __float2half_rn(v1 - __half2float(h1));
                __half l2 = __float2half_rn(v2 - __half2float(h2));
                __half l3 = __float2half_rn(v3 - __half2float(h3));
                *(__half2*)(Ch + (size_t)r0 * N + c) = __halves2half2(h0, h1);
                *(__half2*)(Ch + (size_t)r1 * N + c) = __halves2half2(h2, h3);
                *(__half2*)(Cl + (size_t)r0 * N + c) = __halves2half2(l0, l1);
                *(__half2*)(Cl + (size_t)r1 * N + c) = __halves2half2(l2, l3);
            } else {
                float* Cf = (blockIdx.z == 0) ? (float*)C0v : (float*)C1v;
                *(float2*)(Cf + (size_t)r0 * N + c) = make_float2(v0, v1);
                *(float2*)(Cf + (size_t)r1 * N + c) = make_float2(v2, v3);
            }
        }
    }
}

// ---------------- elementwise kernels ----------------
__device__ __forceinline__ float blockReduceSum(float v) {
    __shared__ float sh[33];
    int lane = threadIdx.x & 31, wid = threadIdx.x >> 5;
    #pragma unroll
    for (int o = 16; o; o >>= 1) v += __shfl_down_sync(0xffffffffu, v, o);
    if (lane == 0) sh[wid] = v;
    __syncthreads();
    if (wid == 0) {
        v = (threadIdx.x < (blockDim.x >> 5)) ? sh[lane] : 0.f;
        #pragma unroll
        for (int o = 16; o; o >>= 1) v += __shfl_down_sync(0xffffffffu, v, o);
        if (lane == 0) sh[32] = v;
    }
    __syncthreads();
    return sh[32];
}

__device__ __forceinline__ void split_store(__half* hi, __half* lo, size_t idx2, float a, float b) {
    __half ha = __float2half_rn(a), hb = __float2half_rn(b);
    __half la = __float2half_rn(a - __half2float(ha));
    __half lb = __float2half_rn(b - __half2float(hb));
    ((__half2*)hi)[idx2] = __halves2half2(ha, hb);
    ((__half2*)lo)[idx2] = __halves2half2(la, lb);
}

// fused: vesica row scale + scaled split of x
__global__ void __launch_bounds__(256) k_scale_split(const float* __restrict__ x) {
    int b  = blockIdx.x;
    int bp = (b == 0) ? (BROWS - 1) : (b - 1);
    const float4* r0 = (const float4*)(x + (size_t)b  * DIN);
    const float4* r1 = (const float4*)(x + (size_t)bp * DIN);
    float ss = 0.f;
    float4 va[2];
    #pragma unroll
    for (int j = 0; j < 2; j++) {
        int i = threadIdx.x + j * 256;
        float4 a = r0[i], c = r1[i];
        va[j] = a;
        float dx = a.x - c.x, dy = a.y - c.y, dz = a.z - c.z, dw = a.w - c.w;
        ss += dx*dx + dy*dy + dz*dz + dw*dw;
    }
    ss = blockReduceSum(ss);          // broadcast
    float dist = sqrtf(ss);
    float s = 1.f + fmaxf(0.f, 1.f - fabsf(dist - 1.f));
    size_t rowBase = (size_t)b * (DIN / 4);
    #pragma unroll
    for (int j = 0; j < 2; j++) {
        size_t i4 = rowBase + threadIdx.x + j * 256;
        split_store(g_xh, g_xl, i4 * 2 + 0, va[j].x * s, va[j].y * s);
        split_store(g_xh, g_xl, i4 * 2 + 1, va[j].z * s, va[j].w * s);
    }
}

__global__ void __launch_bounds__(256) k_split(const float* __restrict__ src,
                                               __half* __restrict__ hi, __half* __restrict__ lo,
                                               size_t n4) {
    size_t i = (size_t)blockIdx.x * 256 + threadIdx.x;
    if (i >= n4) return;
    float4 v = ((const float4*)src)[i];
    split_store(hi, lo, i * 2 + 0, v.x, v.y);
    split_store(hi, lo, i * 2 + 1, v.z, v.w);
}

__global__ void __launch_bounds__(256) k_split_flip(const float* __restrict__ src,
                                                    __half* __restrict__ hi, __half* __restrict__ lo) {
    size_t i = (size_t)blockIdx.x * 256 + threadIdx.x;   // float4 index over [DOUT, DHID]
    if (i >= (size_t)DOUT * DHID / 4) return;
    int o  = (int)(i / (DHID / 4));
    int h4 = (int)(i % (DHID / 4)) * 4;
    float4 v = *(const float4*)(src + (size_t)o * DHID + (DHID - 4 - h4));
    split_store(hi, lo, i * 2 + 0, v.w, v.z);
    split_store(hi, lo, i * 2 + 1, v.y, v.x);
}

__global__ void __launch_bounds__(256) k_final(float* __restrict__ out) {
    int b = blockIdx.x;
    const float4* mr = (const float4*)(g_male + (size_t)b * DOUT);
    const float4* fr = (const float4*)(g_fem  + (size_t)b * DOUT);
    int i0 = threadIdx.x, i1 = threadIdx.x + 256;
    float4 m0 = mr[i0], m1 = mr[i1];
    float4 f0 = fr[i0], f1 = fr[i1];
    float s = m0.x*f0.x + m0.y*f0.y + m0.z*f0.z + m0.w*f0.w
            + m1.x*f1.x + m1.y*f1.y + m1.z*f1.z + m1.w*f1.w;
    s = blockReduceSum(s);
    float pl = 1.f / (1.f + expf(-s));
    float om = 1.f - pl;
    float4* o4 = (float4*)(out + (size_t)b * DOUT);
    o4[i0] = make_float4(pl*m0.x + om*f0.x, pl*m0.y + om*f0.y,
                         pl*m0.z + om*f0.z, pl*m0.w + om*f0.w);
    o4[i1] = make_float4(pl*m1.x + om*f1.x, pl*m1.y + om*f1.y,
                         pl*m1.z + om*f1.z, pl*m1.w + om*f1.w);
}

// ---------------- launch ----------------
extern "C" void kernel_launch(void* const* d_in, const int* in_sizes, int n_in,
                              void* d_out, int out_size) {
    const float* x   = (const float*)d_in[0];   // [4096, 2048]
    const float* wfl = (const float*)d_in[1];   // [3584, 2048]
    const float* wm  = (const float*)d_in[2];   // [2048, 3584]
    const float* wfe = (const float*)d_in[3];   // [2048, 3584]
    float* out = (float*)d_out;

    __half *xh, *xl, *wflh, *wfll, *wmh, *wml, *wfh, *wfl2, *xeh, *xel;
    float *male, *fem;
    cudaGetSymbolAddress((void**)&xh,   g_xh);
    cudaGetSymbolAddress((void**)&xl,   g_xl);
    cudaGetSymbolAddress((void**)&wflh, g_wflh);
    cudaGetSymbolAddress((void**)&wfll, g_wfll);
    cudaGetSymbolAddress((void**)&wmh,  g_wmh);
    cudaGetSymbolAddress((void**)&wml,  g_wml);
    cudaGetSymbolAddress((void**)&wfh,  g_wfh);
    cudaGetSymbolAddress((void**)&wfl2, g_wfl2);
    cudaGetSymbolAddress((void**)&xeh,  g_xeh);
    cudaGetSymbolAddress((void**)&xel,  g_xel);
    cudaGetSymbolAddress((void**)&male, g_male);
    cudaGetSymbolAddress((void**)&fem,  g_fem);

    cudaFuncSetAttribute(gemm_fp16x3<1>, cudaFuncAttributeMaxDynamicSharedMemorySize, GSMEM);
    cudaFuncSetAttribute(gemm_fp16x3<0>, cudaFuncAttributeMaxDynamicSharedMemorySize, GSMEM);

    // 1) vesica scale + x split (fused) and weight splits
    k_scale_split<<<BROWS, 256>>>(x);
    k_split<<<(unsigned)(((size_t)DHID * DIN / 4 + 255) / 256), 256>>>(wfl, wflh, wfll, (size_t)DHID * DIN / 4);
    k_split<<<(unsigned)(((size_t)DOUT * DHID / 4 + 255) / 256), 256>>>(wm, wmh, wml, (size_t)DOUT * DHID / 4);
    k_split_flip<<<(unsigned)(((size_t)DOUT * DHID / 4 + 255) / 256), 256>>>(wfe, wfh, wfl2);

    // 2) GEMM1 (3-term, single-acc): x_expanded with phase epilogue + split write
    {
        dim3 grid(DHID / GBN, BROWS / GBM, 1);
        gemm_fp16x3<1><<<grid, GTHREADS, GSMEM>>>(xh, xl, wflh, wfll, wflh, wfll,
                                                  xeh, xel, DIN, DHID);
    }

    // 3) GEMM2 (3-term, single-acc; z=0 male / z=1 female): xexp @ W^T
    {
        dim3 grid(DOUT / GBN, BROWS / GBM, 2);
        gemm_fp16x3<0><<<grid, GTHREADS, GSMEM>>>(xeh, xel, wmh, wml, wfh, wfl2,
                                                  male, fem, DHID, DOUT);
    }

    // 4) phase-lock blend
    k_final<<<BROWS, 256>>>(out);
}